// round 5
// baseline (speedup 1.0000x reference)
#include <cuda_runtime.h>
#include <math.h>

#define NN    400000
#define NE    1600000
#define FIN   100
#define EMB   128
#define SORTK 64
#define NG    11
#define DCAT  385
#define DENSE 3584
#define FC1IN 39424

typedef unsigned int uint;

/* ---------------- scratch (static device memory; no allocations) ------------- */
__device__ float g_h [NN*EMB];
__device__ float g_x1[NN*EMB];
__device__ float g_x2[NN*EMB];
__device__ float g_x3[NN*EMB];
__device__ float g_x4[NN];
__device__ float g_h4[NN];
__device__ float g_dis[NN];
__device__ int   g_cnt[NN];
__device__ int   g_off[NN];
__device__ int   g_cur[NN];
__device__ int   g_csr_src[NE];
__device__ float g_csr_w[NE];
__device__ int   g_bsum[1024];
__device__ int   g_gcnt[NG];
__device__ int   g_gstart[NG+1];
__device__ int   g_sel[NG*SORTK];
__device__ float g_h5[NG*64*SORTK];
__device__ float g_emb[FC1IN];
__device__ float g_out128[128];

__device__ __forceinline__ float* bufById(int id) {
  return (id==1) ? g_x1 : (id==2) ? g_x2 : g_x3;
}

/* ---------------- tf32 helpers ------------------------------------------------ */
__device__ __forceinline__ uint f2tf32(float x) {
  uint u; asm("cvt.rna.tf32.f32 %0, %1;" : "=r"(u) : "f"(x)); return u;
}
__device__ __forceinline__ void mma_tf32(float* c, const uint* a, uint b0, uint b1) {
  asm volatile("mma.sync.aligned.m16n8k8.row.col.f32.tf32.tf32.f32 "
    "{%0,%1,%2,%3}, {%4,%5,%6,%7}, {%8,%9}, {%0,%1,%2,%3};"
    : "+f"(c[0]), "+f"(c[1]), "+f"(c[2]), "+f"(c[3])
    : "r"(a[0]), "r"(a[1]), "r"(a[2]), "r"(a[3]), "r"(b0), "r"(b1));
}

/* ---------------- init / degree / CSR build ---------------------------------- */
__global__ void k_init() {
  int i = blockIdx.x*blockDim.x + threadIdx.x;
  if (i < NN) { g_cnt[i] = 0; g_cur[i] = 0; }
  if (i < NG) g_gcnt[i] = 0;
  if (i < NG*SORTK) g_sel[i] = -1;
}

__global__ void k_edge_count(const int* __restrict__ ei) {
  int e = blockIdx.x*blockDim.x + threadIdx.x;
  if (e >= NE) return;
  int s = ei[e], d = ei[NE + e];
  if (s != d) atomicAdd(&g_cnt[d], 1);
}

__global__ void k_dis() {
  int i = blockIdx.x*blockDim.x + threadIdx.x;
  if (i < NN) g_dis[i] = rsqrtf((float)g_cnt[i] + 1.0f);
}

__global__ void k_scan1() {
  __shared__ int sh[1024];
  int t = threadIdx.x;
  int i = blockIdx.x*1024 + t;
  int v = (i < NN) ? g_cnt[i] : 0;
  sh[t] = v; __syncthreads();
  for (int d = 1; d < 1024; d <<= 1) {
    int u = (t >= d) ? sh[t-d] : 0;
    __syncthreads();
    sh[t] += u;
    __syncthreads();
  }
  if (i < NN) g_off[i] = sh[t] - v;
  if (t == 1023) g_bsum[blockIdx.x] = sh[1023];
}

__global__ void k_scan2(int nb) {
  __shared__ int sh[1024];
  int t = threadIdx.x;
  int v = (t < nb) ? g_bsum[t] : 0;
  sh[t] = v; __syncthreads();
  for (int d = 1; d < 1024; d <<= 1) {
    int u = (t >= d) ? sh[t-d] : 0;
    __syncthreads();
    sh[t] += u;
    __syncthreads();
  }
  if (t < nb) g_bsum[t] = sh[t] - v;
}

__global__ void k_scan3() {
  int i = blockIdx.x*blockDim.x + threadIdx.x;
  if (i < NN) g_off[i] += g_bsum[i >> 10];
}

__global__ void k_scatter(const int* __restrict__ ei) {
  int e = blockIdx.x*blockDim.x + threadIdx.x;
  if (e >= NE) return;
  int s = ei[e], d = ei[NE + e];
  if (s != d) {
    int p = g_off[d] + atomicAdd(&g_cur[d], 1);
    g_csr_src[p] = s;
    g_csr_w[p]   = g_dis[s]*g_dis[d];
  }
}

__global__ void k_gcount(const int* __restrict__ batch) {
  __shared__ int loc[NG];
  if (threadIdx.x < NG) loc[threadIdx.x] = 0;
  __syncthreads();
  int i = blockIdx.x*blockDim.x + threadIdx.x;
  if (i < NN) atomicAdd(&loc[batch[i]], 1);
  __syncthreads();
  if (threadIdx.x < NG) atomicAdd(&g_gcnt[threadIdx.x], loc[threadIdx.x]);
}

__global__ void k_gstart() {
  if (threadIdx.x == 0 && blockIdx.x == 0) {
    int a = 0;
    for (int g = 0; g < NG; ++g) { g_gstart[g] = a; a += g_gcnt[g]; }
    g_gstart[NG] = a;
  }
}

/* ---------------- GEMM via mma.sync tf32 (3xTF32 split) ----------------------- */
/* H[128-tile, 128] = X[tile, K] @ W[K, 128].  8 warps, warp tile 32x64.          */
/* smem: AsH/AsL [128][36], BsH/BsL [128][36] words (pad 36 -> conflict-free).    */
#define SPITCH 36
#define GEMM_SMEM_W (4*128*SPITCH)

__global__ __launch_bounds__(256) void k_gemm_mma(const float* __restrict__ Xext,
                                                  int xbuf,
                                                  const float* __restrict__ W,
                                                  int K) {
  extern __shared__ uint sm[];
  uint* AsH = sm;
  uint* AsL = sm + 128*SPITCH;
  uint* BsH = sm + 2*128*SPITCH;
  uint* BsL = sm + 3*128*SPITCH;

  const float* __restrict__ X = Xext ? Xext : bufById(xbuf);
  const int tid  = threadIdx.x;
  const int lane = tid & 31;
  const int wid  = tid >> 5;
  const int wr   = wid >> 1;        /* 0..3 : 32-row slab  */
  const int wc   = wid & 1;         /* 0..1 : 64-col slab  */
  const int row0 = blockIdx.x * 128;

  float acc[2][8][4];
  #pragma unroll
  for (int mt = 0; mt < 2; ++mt)
    #pragma unroll
    for (int nt = 0; nt < 8; ++nt)
      #pragma unroll
      for (int j = 0; j < 4; ++j) acc[mt][nt][j] = 0.f;

  const int lr = lane >> 2;         /* 0..7 */
  const int lk = lane & 3;          /* 0..3 */

  for (int k0 = 0; k0 < 128; k0 += 32) {
    /* fill A: 128 rows x 32 k, split tf32 hi/lo */
    #pragma unroll
    for (int it = 0; it < 16; ++it) {
      int idx = tid + it*256;
      int r = idx >> 5, k = idx & 31;
      float v = (k0 + k < K) ? X[(size_t)(row0 + r)*K + k0 + k] : 0.f;
      uint hi = f2tf32(v);
      uint lo = f2tf32(v - __uint_as_float(hi));
      AsH[r*SPITCH + k] = hi;
      AsL[r*SPITCH + k] = lo;
    }
    /* fill B (transpose): Bs[n][k] from W[k][n] */
    #pragma unroll
    for (int it = 0; it < 16; ++it) {
      int idx = tid + it*256;
      int n = idx & 127, k = idx >> 7;
      float v = (k0 + k < K) ? W[(size_t)(k0 + k)*128 + n] : 0.f;
      uint hi = f2tf32(v);
      uint lo = f2tf32(v - __uint_as_float(hi));
      BsH[n*SPITCH + k] = hi;
      BsL[n*SPITCH + k] = lo;
    }
    __syncthreads();

    #pragma unroll
    for (int ks = 0; ks < 4; ++ks) {
      const int kb = ks*8;
      uint aH[2][4], aL[2][4];
      #pragma unroll
      for (int mt = 0; mt < 2; ++mt) {
        int r = wr*32 + mt*16 + lr;
        int kk = kb + lk;
        aH[mt][0] = AsH[r*SPITCH + kk];
        aH[mt][1] = AsH[(r+8)*SPITCH + kk];
        aH[mt][2] = AsH[r*SPITCH + kk + 4];
        aH[mt][3] = AsH[(r+8)*SPITCH + kk + 4];
        aL[mt][0] = AsL[r*SPITCH + kk];
        aL[mt][1] = AsL[(r+8)*SPITCH + kk];
        aL[mt][2] = AsL[r*SPITCH + kk + 4];
        aL[mt][3] = AsL[(r+8)*SPITCH + kk + 4];
      }
      #pragma unroll
      for (int nt = 0; nt < 8; ++nt) {
        int n = wc*64 + nt*8 + lr;
        int kk = kb + lk;
        uint bH0 = BsH[n*SPITCH + kk], bH1 = BsH[n*SPITCH + kk + 4];
        uint bL0 = BsL[n*SPITCH + kk], bL1 = BsL[n*SPITCH + kk + 4];
        #pragma unroll
        for (int mt = 0; mt < 2; ++mt) {
          mma_tf32(acc[mt][nt], aH[mt], bH0, bH1);
          mma_tf32(acc[mt][nt], aH[mt], bL0, bL1);
          mma_tf32(acc[mt][nt], aL[mt], bH0, bH1);
        }
      }
    }
    __syncthreads();
  }

  /* epilogue: direct float2 stores */
  #pragma unroll
  for (int mt = 0; mt < 2; ++mt) {
    int r = row0 + wr*32 + mt*16 + lr;
    #pragma unroll
    for (int nt = 0; nt < 8; ++nt) {
      int c = wc*64 + nt*8 + lk*2;
      *(float2*)&g_h[(size_t)r*EMB + c]      = make_float2(acc[mt][nt][0], acc[mt][nt][1]);
      *(float2*)&g_h[(size_t)(r+8)*EMB + c]  = make_float2(acc[mt][nt][2], acc[mt][nt][3]);
    }
  }
}

/* ---------------- aggregation + self term + bias + tanh ----------------------- */
__global__ void k_agg_tanh(const float* __restrict__ bias, int outId) {
  int warp = (blockIdx.x*blockDim.x + threadIdx.x) >> 5;
  if (warp >= NN) return;
  int lane = threadIdx.x & 31;
  int n = warp;
  float4 acc = make_float4(0.f,0.f,0.f,0.f);
  int b = g_off[n], e = b + g_cnt[n];
  for (int j = b; j < e; ++j) {
    int   s = g_csr_src[j];
    float w = g_csr_w[j];
    float4 hv = *(const float4*)(g_h + (size_t)s*EMB + lane*4);
    acc.x += w*hv.x; acc.y += w*hv.y; acc.z += w*hv.z; acc.w += w*hv.w;
  }
  float di = g_dis[n]; float sn = di*di;
  float4 hv = *(const float4*)(g_h + (size_t)n*EMB + lane*4);
  float4 bv = *(const float4*)(bias + lane*4);
  float4 o;
  o.x = tanhf(acc.x + sn*hv.x + bv.x);
  o.y = tanhf(acc.y + sn*hv.y + bv.y);
  o.z = tanhf(acc.z + sn*hv.z + bv.z);
  o.w = tanhf(acc.w + sn*hv.w + bv.w);
  *(float4*)(bufById(outId) + (size_t)n*EMB + lane*4) = o;
}

/* ---------------- layer 4 (EMB -> 1) ------------------------------------------ */
__global__ void k_h4(const float* __restrict__ W4) {
  int warp = (blockIdx.x*blockDim.x + threadIdx.x) >> 5;
  if (warp >= NN) return;
  int lane = threadIdx.x & 31;
  float4 xv = *(const float4*)(g_x3 + (size_t)warp*EMB + lane*4);
  float4 wv = *(const float4*)(W4 + lane*4);
  float a = xv.x*wv.x + xv.y*wv.y + xv.z*wv.z + xv.w*wv.w;
  #pragma unroll
  for (int d = 16; d; d >>= 1) a += __shfl_down_sync(0xffffffffu, a, d);
  if (lane == 0) g_h4[warp] = a;
}

__global__ void k_agg4(const float* __restrict__ b4) {
  int n = blockIdx.x*blockDim.x + threadIdx.x;
  if (n >= NN) return;
  float acc = 0.f;
  int b = g_off[n], e = b + g_cnt[n];
  for (int j = b; j < e; ++j) acc += g_csr_w[j]*g_h4[g_csr_src[j]];
  float di = g_dis[n];
  g_x4[n] = tanhf(acc + g_h4[n]*di*di + b4[0]);
}

/* ---------------- per-graph exact top-64 (desc score, stable by index) -------- */
__device__ __forceinline__ unsigned keyOf(float f) {
  unsigned u = __float_as_uint(f);
  return (u & 0x80000000u) ? ~u : (u | 0x80000000u);
}

__global__ void k_select() {
  const int g = blockIdx.x;
  const int s = g_gstart[g], e = g_gstart[g+1];
  const int n = e - s;
  const int tid = threadIdx.x;
  const int NT = blockDim.x;

  __shared__ int      selIdx[SORTK];
  __shared__ unsigned selKey[SORTK];
  __shared__ int      red[32];
  __shared__ unsigned shPrefix;
  __shared__ int      shRem, shCg;

  if (tid < SORTK) { selIdx[tid] = -1; selKey[tid] = 0u; }
  if (tid == 0)    { shPrefix = 0u; shRem = SORTK; shCg = 0; }
  __syncthreads();

  if (n <= SORTK) {
    if (tid < n) { selIdx[tid] = s + tid; selKey[tid] = keyOf(g_x4[s+tid]); }
    __syncthreads();
  } else {
    for (int bit = 31; bit >= 0; --bit) {
      unsigned cand = shPrefix | (1u << bit);
      unsigned mask = ~((1u << bit) - 1u);
      int c = 0;
      for (int i = s + tid; i < e; i += NT)
        c += ((keyOf(g_x4[i]) & mask) == cand) ? 1 : 0;
      #pragma unroll
      for (int d = 16; d; d >>= 1) c += __shfl_down_sync(0xffffffffu, c, d);
      if ((tid & 31) == 0) red[tid >> 5] = c;
      __syncthreads();
      if (tid == 0) {
        int tot = 0;
        for (int w = 0; w < (NT >> 5); ++w) tot += red[w];
        if (tot >= shRem) shPrefix = cand; else shRem -= tot;
      }
      __syncthreads();
    }
    unsigned Tk = shPrefix;
    for (int i = s + tid; i < e; i += NT) {
      unsigned k = keyOf(g_x4[i]);
      if (k > Tk) {
        int p = atomicAdd(&shCg, 1);
        selIdx[p] = i; selKey[p] = k;
      }
    }
    __syncthreads();
    int cg = shCg;
    int need = SORTK - cg;
    for (int i = s + tid; i < e; i += NT) {
      if (keyOf(g_x4[i]) == Tk) {
        int r = 0;
        for (int j = s; j < i; ++j) r += (keyOf(g_x4[j]) == Tk) ? 1 : 0;
        if (r < need) { selIdx[cg + r] = i; selKey[cg + r] = Tk; }
      }
    }
    __syncthreads();
  }

  if (tid < SORTK) {
    int mi = selIdx[tid];
    if (mi >= 0) {
      unsigned mk = selKey[tid];
      int r = 0;
      for (int j = 0; j < SORTK; ++j) {
        int ij = selIdx[j]; if (ij < 0) continue;
        unsigned kj = selKey[j];
        if (kj > mk || (kj == mk && ij < mi)) ++r;
      }
      g_sel[g*SORTK + r] = mi;
    }
  }
}

/* ---------------- conv5 (385 -> 64 per sorted row) + relu --------------------- */
__global__ void k_conv5(const float* __restrict__ cw5, const float* __restrict__ cb5) {
  __shared__ float row[DCAT];
  int g = blockIdx.x / SORTK, k = blockIdx.x % SORTK;
  int m = g_sel[g*SORTK + k];
  int tid = threadIdx.x;
  for (int d = tid; d < DCAT; d += 128) {
    float v = 0.f;
    if (m >= 0) {
      if      (d < 128) v = g_x1[(size_t)m*EMB + d];
      else if (d < 256) v = g_x2[(size_t)m*EMB + d - 128];
      else if (d < 384) v = g_x3[(size_t)m*EMB + d - 256];
      else              v = g_x4[m];
    }
    row[d] = v;
  }
  __syncthreads();
  if (tid < 64) {
    float acc = cb5[tid];
    const float* w = cw5 + tid*DCAT;
    for (int d = 0; d < DCAT; ++d) acc += w[d]*row[d];
    g_h5[((size_t)g*64 + tid)*SORTK + k] = fmaxf(acc, 0.f);
  }
}

/* ---------------- maxpool(2) + conv6(k=5) + relu -> emb ----------------------- */
__global__ void k_conv6(const float* __restrict__ cw6, const float* __restrict__ cb6) {
  __shared__ float hp[64*32];
  int g = blockIdx.x, tid = threadIdx.x;
  for (int i = tid; i < 64*32; i += 128) {
    int ci = i >> 5, j = i & 31;
    const float* hr = g_h5 + ((size_t)g*64 + ci)*SORTK + 2*j;
    hp[ci*32 + j] = fmaxf(hr[0], hr[1]);
  }
  __syncthreads();
  int o = tid;
  const float* w = cw6 + (size_t)o*64*5;
  for (int l = 0; l < 28; ++l) {
    float acc = cb6[o];
    for (int ci = 0; ci < 64; ++ci) {
      const float* hh = hp + ci*32 + l;
      const float* wc = w + ci*5;
      acc += wc[0]*hh[0] + wc[1]*hh[1] + wc[2]*hh[2] + wc[3]*hh[3] + wc[4]*hh[4];
    }
    g_emb[(size_t)g*DENSE + o*28 + l] = fmaxf(acc, 0.f);
  }
}

/* ---------------- fc1 (39424 -> 128) + relu ----------------------------------- */
__global__ void k_fc1(const float* __restrict__ fw1, const float* __restrict__ fb1) {
  int o = blockIdx.x, tid = threadIdx.x;
  float acc = 0.f;
  const float* w = fw1 + (size_t)o*FC1IN;
  for (int i = tid; i < FC1IN; i += 256) acc += g_emb[i]*w[i];
  __shared__ float sh[8];
  #pragma unroll
  for (int d = 16; d; d >>= 1) acc += __shfl_down_sync(0xffffffffu, acc, d);
  if ((tid & 31) == 0) sh[tid >> 5] = acc;
  __syncthreads();
  if (tid < 8) {
    float v = sh[tid];
    #pragma unroll
    for (int d = 4; d; d >>= 1) v += __shfl_down_sync(0x000000ffu, v, d);
    if (tid == 0) g_out128[o] = fmaxf(v + fb1[o], 0.f);
  }
}

/* ---------------- fc2 (128 -> 10) --------------------------------------------- */
__global__ void k_fc2(const float* __restrict__ fw2, const float* __restrict__ fb2,
                      float* __restrict__ out) {
  int t = threadIdx.x >> 5, lane = threadIdx.x & 31;
  if (t >= 10) return;
  float acc = 0.f;
  for (int i = lane; i < 128; i += 32) acc += g_out128[i]*fw2[t*128 + i];
  #pragma unroll
  for (int d = 16; d; d >>= 1) acc += __shfl_down_sync(0xffffffffu, acc, d);
  if (lane == 0) out[t] = acc + fb2[t];
}

/* ---------------- host orchestration ------------------------------------------ */
extern "C" void kernel_launch(void* const* d_in, const int* in_sizes, int n_in,
                              void* d_out, int out_size) {
  const float* x     = (const float*)d_in[0];
  const int*   ei    = (const int*)  d_in[1];
  const int*   batch = (const int*)  d_in[2];
  const float* W1 = (const float*)d_in[3],  *b1  = (const float*)d_in[4];
  const float* W2 = (const float*)d_in[5],  *b2  = (const float*)d_in[6];
  const float* W3 = (const float*)d_in[7],  *b3  = (const float*)d_in[8];
  const float* W4 = (const float*)d_in[9],  *b4  = (const float*)d_in[10];
  const float* cw5= (const float*)d_in[11], *cb5 = (const float*)d_in[12];
  const float* cw6= (const float*)d_in[13], *cb6 = (const float*)d_in[14];
  const float* fw1= (const float*)d_in[15], *fb1 = (const float*)d_in[16];
  const float* fw2= (const float*)d_in[17], *fb2 = (const float*)d_in[18];
  float* logits = (float*)d_out;

  const int GEMM_SMEM = GEMM_SMEM_W * 4;   /* 73728 bytes */
  static int attrDone = 0;
  if (!attrDone) {
    cudaFuncSetAttribute(k_gemm_mma, cudaFuncAttributeMaxDynamicSharedMemorySize, GEMM_SMEM);
    attrDone = 1;
  }

  const int TB = 256;
  const int nbN  = (NN + TB - 1)/TB;
  const int nbE  = (NE + TB - 1)/TB;
  const int nbW  = (NN*32 + TB - 1)/TB;
  const int nbSc = (NN + 1023)/1024;

  k_init      <<<nbN, TB>>>();
  k_edge_count<<<nbE, TB>>>(ei);
  k_dis       <<<nbN, TB>>>();
  k_scan1     <<<nbSc, 1024>>>();
  k_scan2     <<<1, 1024>>>(nbSc);
  k_scan3     <<<nbN, TB>>>();
  k_scatter   <<<nbE, TB>>>(ei);
  k_gcount    <<<nbN, TB>>>(batch);
  k_gstart    <<<1, 32>>>();

  const int gemmGrid = NN/128;   /* 3125, exact */
  k_gemm_mma <<<gemmGrid, 256, GEMM_SMEM>>>(x, 0, W1, FIN);
  k_agg_tanh <<<nbW, TB>>>(b1, 1);
  k_gemm_mma <<<gemmGrid, 256, GEMM_SMEM>>>(nullptr, 1, W2, EMB);
  k_agg_tanh <<<nbW, TB>>>(b2, 2);
  k_gemm_mma <<<gemmGrid, 256, GEMM_SMEM>>>(nullptr, 2, W3, EMB);
  k_agg_tanh <<<nbW, TB>>>(b3, 3);
  k_h4       <<<nbW, TB>>>(W4);
  k_agg4     <<<nbN, TB>>>(b4);

  k_select <<<NG, 1024>>>();
  k_conv5  <<<NG*SORTK, 128>>>(cw5, cb5);
  k_conv6  <<<NG, 128>>>(cw6, cb6);
  k_fc1    <<<128, 256>>>(fw1, fb1);
  k_fc2    <<<1, 320>>>(fw2, fb2, logits);
}

// round 6
// speedup vs baseline: 1.0253x; 1.0253x over previous
#include <cuda_runtime.h>
#include <math.h>

#define NN    400000
#define NE    1600000
#define FIN   100
#define EMB   128
#define SORTK 64
#define NG    11
#define DCAT  385
#define DENSE 3584
#define FC1IN 39424

typedef unsigned long long ull;
typedef unsigned int uint;

/* ---------------- scratch (static device memory; no allocations) ------------- */
__device__ float g_h [NN*EMB];
__device__ float g_x1[NN*EMB];
__device__ float g_x2[NN*EMB];
__device__ float g_x3[NN*EMB];
__device__ float g_x4[NN];
__device__ float g_h4[NN];
__device__ float g_dis[NN];
__device__ int   g_cnt[NN];
__device__ int   g_off[NN];
__device__ int   g_cur[NN];
__device__ int2  g_csr[NE];          /* (src, w-as-int) packed */
__device__ int   g_bsum[1024];
__device__ int   g_gcnt[NG];
__device__ int   g_gstart[NG+1];
__device__ int   g_sel[NG*SORTK];
__device__ float g_h5[NG*64*SORTK];
__device__ float g_emb[FC1IN];
__device__ float g_out128[128];

__device__ __forceinline__ float* bufById(int id) {
  return (id==1) ? g_x1 : (id==2) ? g_x2 : g_x3;
}

/* ---------------- f32x2 packed helpers (sm_103a) ------------------------------ */
__device__ __forceinline__ void ffma2(ull& d, ull a, ull b) {
  asm("fma.rn.f32x2 %0, %1, %2, %0;" : "+l"(d) : "l"(a), "l"(b));
}
__device__ __forceinline__ ull dup2(float x) {
  ull r; asm("mov.b64 %0, {%1, %1};" : "=l"(r) : "f"(x)); return r;
}
__device__ __forceinline__ float2 unpack2(ull v) {
  float2 f; asm("mov.b64 {%0, %1}, %2;" : "=f"(f.x), "=f"(f.y) : "l"(v)); return f;
}

/* ---------------- init / degree / CSR build ---------------------------------- */
__global__ void k_init() {
  int i = blockIdx.x*blockDim.x + threadIdx.x;
  if (i < NN) { g_cnt[i] = 0; g_cur[i] = 0; }
  if (i < NG) g_gcnt[i] = 0;
  if (i < NG*SORTK) g_sel[i] = -1;
}

__global__ void k_edge_count(const int* __restrict__ ei) {
  int e = blockIdx.x*blockDim.x + threadIdx.x;
  if (e >= NE) return;
  int s = ei[e], d = ei[NE + e];
  if (s != d) atomicAdd(&g_cnt[d], 1);
}

__global__ void k_dis() {
  int i = blockIdx.x*blockDim.x + threadIdx.x;
  if (i < NN) g_dis[i] = rsqrtf((float)g_cnt[i] + 1.0f);
}

__global__ void k_scan1() {
  __shared__ int sh[1024];
  int t = threadIdx.x;
  int i = blockIdx.x*1024 + t;
  int v = (i < NN) ? g_cnt[i] : 0;
  sh[t] = v; __syncthreads();
  for (int d = 1; d < 1024; d <<= 1) {
    int u = (t >= d) ? sh[t-d] : 0;
    __syncthreads();
    sh[t] += u;
    __syncthreads();
  }
  if (i < NN) g_off[i] = sh[t] - v;
  if (t == 1023) g_bsum[blockIdx.x] = sh[1023];
}

__global__ void k_scan2(int nb) {
  __shared__ int sh[1024];
  int t = threadIdx.x;
  int v = (t < nb) ? g_bsum[t] : 0;
  sh[t] = v; __syncthreads();
  for (int d = 1; d < 1024; d <<= 1) {
    int u = (t >= d) ? sh[t-d] : 0;
    __syncthreads();
    sh[t] += u;
    __syncthreads();
  }
  if (t < nb) g_bsum[t] = sh[t] - v;
}

__global__ void k_scan3() {
  int i = blockIdx.x*blockDim.x + threadIdx.x;
  if (i < NN) g_off[i] += g_bsum[i >> 10];
}

__global__ void k_scatter(const int* __restrict__ ei) {
  int e = blockIdx.x*blockDim.x + threadIdx.x;
  if (e >= NE) return;
  int s = ei[e], d = ei[NE + e];
  if (s != d) {
    int p = g_off[d] + atomicAdd(&g_cur[d], 1);
    float w = g_dis[s]*g_dis[d];
    g_csr[p] = make_int2(s, __float_as_int(w));
  }
}

__global__ void k_gcount(const int* __restrict__ batch) {
  __shared__ int loc[NG];
  if (threadIdx.x < NG) loc[threadIdx.x] = 0;
  __syncthreads();
  int i = blockIdx.x*blockDim.x + threadIdx.x;
  if (i < NN) atomicAdd(&loc[batch[i]], 1);
  __syncthreads();
  if (threadIdx.x < NG) atomicAdd(&g_gcnt[threadIdx.x], loc[threadIdx.x]);
}

__global__ void k_gstart() {
  if (threadIdx.x == 0 && blockIdx.x == 0) {
    int a = 0;
    for (int g = 0; g < NG; ++g) { g_gstart[g] = a; a += g_gcnt[g]; }
    g_gstart[NG] = a;
  }
}

/* ---------------- GEMM: H[nrows,128] = X[nrows,K] @ W[K,128] (FFMA2) ---------- */
__global__ __launch_bounds__(256, 2) void k_gemm(const float* __restrict__ Xext, int xbuf,
                                                 const float* __restrict__ W, int K) {
  __shared__ float Xs[128*32];   /* Xs[r*32 + k] */
  __shared__ float Ws[32*128];   /* Ws[k*128 + c] */
  const float* __restrict__ X = Xext ? Xext : bufById(xbuf);
  const int tid = threadIdx.x;
  const int tr  = tid >> 4;
  const int tc  = tid & 15;
  const int r0  = tr * 8;
  const int c0  = tc * 8;
  const int row0 = blockIdx.x * 128;

  ull acc[8][4];
  #pragma unroll
  for (int r = 0; r < 8; ++r)
    #pragma unroll
    for (int j = 0; j < 4; ++j) acc[r][j] = 0ull;

  for (int k0 = 0; k0 < K; k0 += 32) {
    const int kc = min(32, K - k0);
    {
      const float4* src = (const float4*)(W + (size_t)k0*128);
      float4* dst = (float4*)Ws;
      for (int i = tid; i < kc*32; i += 256) dst[i] = src[i];
    }
    if (kc == 32) {
      for (int i = tid; i < 128*32; i += 256) {
        int r = i >> 5, k = i & 31;
        Xs[i] = X[(size_t)(row0 + r)*K + k0 + k];
      }
    } else {
      for (int i = tid; i < 128*kc; i += 256) {
        int r = i / kc, k = i - r*kc;
        Xs[r*32 + k] = X[(size_t)(row0 + r)*K + k0 + k];
      }
    }
    __syncthreads();

    #pragma unroll 4
    for (int k = 0; k < kc; ++k) {
      ull w[4];
      const ull* wp = (const ull*)(Ws + k*128 + c0);
      w[0] = wp[0]; w[1] = wp[1]; w[2] = wp[2]; w[3] = wp[3];
      #pragma unroll
      for (int r = 0; r < 8; ++r) {
        ull xd = dup2(Xs[(r0 + r)*32 + k]);
        ffma2(acc[r][0], xd, w[0]);
        ffma2(acc[r][1], xd, w[1]);
        ffma2(acc[r][2], xd, w[2]);
        ffma2(acc[r][3], xd, w[3]);
      }
    }
    __syncthreads();
  }

  #pragma unroll
  for (int r = 0; r < 8; ++r) {
    int gr = row0 + r0 + r;
    float2 a0 = unpack2(acc[r][0]), a1 = unpack2(acc[r][1]);
    float2 a2 = unpack2(acc[r][2]), a3 = unpack2(acc[r][3]);
    *(float4*)&g_h[(size_t)gr*EMB + c0]     = make_float4(a0.x, a0.y, a1.x, a1.y);
    *(float4*)&g_h[(size_t)gr*EMB + c0 + 4] = make_float4(a2.x, a2.y, a3.x, a3.y);
  }
}

/* ---------------- aggregation + self term + bias + tanh (+ fused h4) ---------- */
/* one warp per node; unroll-4 gather for MLP; optional fused x3.W4 dot.          */
__global__ void k_agg_tanh(const float* __restrict__ bias, int outId,
                           const float* __restrict__ W4) {
  int n = (blockIdx.x*blockDim.x + threadIdx.x) >> 5;
  if (n >= NN) return;
  int lane = threadIdx.x & 31;
  const int co = lane*4;

  int b = g_off[n], e = b + g_cnt[n];
  float di = g_dis[n];
  /* hoist self row (issues before gather loop) */
  float4 self = *(const float4*)(g_h + (size_t)n*EMB + co);

  float4 acc = make_float4(0.f,0.f,0.f,0.f);
  int j = b;
  for (; j + 4 <= e; j += 4) {
    int2 e0 = g_csr[j],   e1 = g_csr[j+1];
    int2 e2 = g_csr[j+2], e3 = g_csr[j+3];
    float4 h0 = *(const float4*)(g_h + (size_t)e0.x*EMB + co);
    float4 h1 = *(const float4*)(g_h + (size_t)e1.x*EMB + co);
    float4 h2 = *(const float4*)(g_h + (size_t)e2.x*EMB + co);
    float4 h3 = *(const float4*)(g_h + (size_t)e3.x*EMB + co);
    float w0 = __int_as_float(e0.y), w1 = __int_as_float(e1.y);
    float w2 = __int_as_float(e2.y), w3 = __int_as_float(e3.y);
    acc.x += w0*h0.x + w1*h1.x + w2*h2.x + w3*h3.x;
    acc.y += w0*h0.y + w1*h1.y + w2*h2.y + w3*h3.y;
    acc.z += w0*h0.z + w1*h1.z + w2*h2.z + w3*h3.z;
    acc.w += w0*h0.w + w1*h1.w + w2*h2.w + w3*h3.w;
  }
  for (; j < e; ++j) {
    int2 ee = g_csr[j];
    float w = __int_as_float(ee.y);
    float4 hv = *(const float4*)(g_h + (size_t)ee.x*EMB + co);
    acc.x += w*hv.x; acc.y += w*hv.y; acc.z += w*hv.z; acc.w += w*hv.w;
  }

  float sn = di*di;
  float4 bv = *(const float4*)(bias + co);
  float4 o;
  o.x = tanhf(acc.x + sn*self.x + bv.x);
  o.y = tanhf(acc.y + sn*self.y + bv.y);
  o.z = tanhf(acc.z + sn*self.z + bv.z);
  o.w = tanhf(acc.w + sn*self.w + bv.w);
  *(float4*)(bufById(outId) + (size_t)n*EMB + co) = o;

  if (W4) {   /* layer-3 fusion: h4[n] = dot(x3[n], W4) */
    float4 wv = *(const float4*)(W4 + co);
    float a = o.x*wv.x + o.y*wv.y + o.z*wv.z + o.w*wv.w;
    #pragma unroll
    for (int d = 16; d; d >>= 1) a += __shfl_down_sync(0xffffffffu, a, d);
    if (lane == 0) g_h4[n] = a;
  }
}

/* ---------------- layer 4 aggregation (scalar) -------------------------------- */
__global__ void k_agg4(const float* __restrict__ b4) {
  int n = blockIdx.x*blockDim.x + threadIdx.x;
  if (n >= NN) return;
  float acc = 0.f;
  int b = g_off[n], e = b + g_cnt[n];
  int j = b;
  for (; j + 2 <= e; j += 2) {
    int2 e0 = g_csr[j], e1 = g_csr[j+1];
    float v0 = g_h4[e0.x], v1 = g_h4[e1.x];
    acc += __int_as_float(e0.y)*v0 + __int_as_float(e1.y)*v1;
  }
  if (j < e) {
    int2 e0 = g_csr[j];
    acc += __int_as_float(e0.y)*g_h4[e0.x];
  }
  float di = g_dis[n];
  g_x4[n] = tanhf(acc + g_h4[n]*di*di + b4[0]);
}

/* ---------------- per-graph exact top-64 (desc score, stable by index) -------- */
__device__ __forceinline__ unsigned keyOf(float f) {
  unsigned u = __float_as_uint(f);
  return (u & 0x80000000u) ? ~u : (u | 0x80000000u);
}

__global__ void k_select() {
  const int g = blockIdx.x;
  const int s = g_gstart[g], e = g_gstart[g+1];
  const int n = e - s;
  const int tid = threadIdx.x;
  const int NT = blockDim.x;

  __shared__ int      selIdx[SORTK];
  __shared__ unsigned selKey[SORTK];
  __shared__ int      red[32];
  __shared__ unsigned shPrefix;
  __shared__ int      shRem, shCg;

  if (tid < SORTK) { selIdx[tid] = -1; selKey[tid] = 0u; }
  if (tid == 0)    { shPrefix = 0u; shRem = SORTK; shCg = 0; }
  __syncthreads();

  if (n <= SORTK) {
    if (tid < n) { selIdx[tid] = s + tid; selKey[tid] = keyOf(g_x4[s+tid]); }
    __syncthreads();
  } else {
    for (int bit = 31; bit >= 0; --bit) {
      unsigned cand = shPrefix | (1u << bit);
      unsigned mask = ~((1u << bit) - 1u);
      int c = 0;
      for (int i = s + tid; i < e; i += NT)
        c += ((keyOf(g_x4[i]) & mask) == cand) ? 1 : 0;
      #pragma unroll
      for (int d = 16; d; d >>= 1) c += __shfl_down_sync(0xffffffffu, c, d);
      if ((tid & 31) == 0) red[tid >> 5] = c;
      __syncthreads();
      if (tid == 0) {
        int tot = 0;
        for (int w = 0; w < (NT >> 5); ++w) tot += red[w];
        if (tot >= shRem) shPrefix = cand; else shRem -= tot;
      }
      __syncthreads();
    }
    unsigned Tk = shPrefix;
    for (int i = s + tid; i < e; i += NT) {
      unsigned k = keyOf(g_x4[i]);
      if (k > Tk) {
        int p = atomicAdd(&shCg, 1);
        selIdx[p] = i; selKey[p] = k;
      }
    }
    __syncthreads();
    int cg = shCg;
    int need = SORTK - cg;
    for (int i = s + tid; i < e; i += NT) {
      if (keyOf(g_x4[i]) == Tk) {
        int r = 0;
        for (int j = s; j < i; ++j) r += (keyOf(g_x4[j]) == Tk) ? 1 : 0;
        if (r < need) { selIdx[cg + r] = i; selKey[cg + r] = Tk; }
      }
    }
    __syncthreads();
  }

  if (tid < SORTK) {
    int mi = selIdx[tid];
    if (mi >= 0) {
      unsigned mk = selKey[tid];
      int r = 0;
      for (int j = 0; j < SORTK; ++j) {
        int ij = selIdx[j]; if (ij < 0) continue;
        unsigned kj = selKey[j];
        if (kj > mk || (kj == mk && ij < mi)) ++r;
      }
      g_sel[g*SORTK + r] = mi;
    }
  }
}

/* ---------------- conv5 (385 -> 64 per sorted row) + relu --------------------- */
__global__ void k_conv5(const float* __restrict__ cw5, const float* __restrict__ cb5) {
  __shared__ float row[DCAT];
  int g = blockIdx.x / SORTK, k = blockIdx.x % SORTK;
  int m = g_sel[g*SORTK + k];
  int tid = threadIdx.x;
  for (int d = tid; d < DCAT; d += 128) {
    float v = 0.f;
    if (m >= 0) {
      if      (d < 128) v = g_x1[(size_t)m*EMB + d];
      else if (d < 256) v = g_x2[(size_t)m*EMB + d - 128];
      else if (d < 384) v = g_x3[(size_t)m*EMB + d - 256];
      else              v = g_x4[m];
    }
    row[d] = v;
  }
  __syncthreads();
  if (tid < 64) {
    float acc = cb5[tid];
    const float* w = cw5 + tid*DCAT;
    for (int d = 0; d < DCAT; ++d) acc += w[d]*row[d];
    g_h5[((size_t)g*64 + tid)*SORTK + k] = fmaxf(acc, 0.f);
  }
}

/* ---------------- maxpool(2) + conv6(k=5) + relu -> emb ----------------------- */
__global__ void k_conv6(const float* __restrict__ cw6, const float* __restrict__ cb6) {
  __shared__ float hp[64*32];
  int g = blockIdx.x, tid = threadIdx.x;
  for (int i = tid; i < 64*32; i += 128) {
    int ci = i >> 5, j = i & 31;
    const float* hr = g_h5 + ((size_t)g*64 + ci)*SORTK + 2*j;
    hp[ci*32 + j] = fmaxf(hr[0], hr[1]);
  }
  __syncthreads();
  int o = tid;
  const float* w = cw6 + (size_t)o*64*5;
  for (int l = 0; l < 28; ++l) {
    float acc = cb6[o];
    for (int ci = 0; ci < 64; ++ci) {
      const float* hh = hp + ci*32 + l;
      const float* wc = w + ci*5;
      acc += wc[0]*hh[0] + wc[1]*hh[1] + wc[2]*hh[2] + wc[3]*hh[3] + wc[4]*hh[4];
    }
    g_emb[(size_t)g*DENSE + o*28 + l] = fmaxf(acc, 0.f);
  }
}

/* ---------------- fc1 (39424 -> 128) + relu ----------------------------------- */
__global__ void k_fc1(const float* __restrict__ fw1, const float* __restrict__ fb1) {
  int o = blockIdx.x, tid = threadIdx.x;
  float acc = 0.f;
  const float* w = fw1 + (size_t)o*FC1IN;
  for (int i = tid; i < FC1IN; i += 256) acc += g_emb[i]*w[i];
  __shared__ float sh[8];
  #pragma unroll
  for (int d = 16; d; d >>= 1) acc += __shfl_down_sync(0xffffffffu, acc, d);
  if ((tid & 31) == 0) sh[tid >> 5] = acc;
  __syncthreads();
  if (tid < 8) {
    float v = sh[tid];
    #pragma unroll
    for (int d = 4; d; d >>= 1) v += __shfl_down_sync(0x000000ffu, v, d);
    if (tid == 0) g_out128[o] = fmaxf(v + fb1[o], 0.f);
  }
}

/* ---------------- fc2 (128 -> 10) --------------------------------------------- */
__global__ void k_fc2(const float* __restrict__ fw2, const float* __restrict__ fb2,
                      float* __restrict__ out) {
  int t = threadIdx.x >> 5, lane = threadIdx.x & 31;
  if (t >= 10) return;
  float acc = 0.f;
  for (int i = lane; i < 128; i += 32) acc += g_out128[i]*fw2[t*128 + i];
  #pragma unroll
  for (int d = 16; d; d >>= 1) acc += __shfl_down_sync(0xffffffffu, acc, d);
  if (lane == 0) out[t] = acc + fb2[t];
}

/* ---------------- host orchestration ------------------------------------------ */
extern "C" void kernel_launch(void* const* d_in, const int* in_sizes, int n_in,
                              void* d_out, int out_size) {
  const float* x     = (const float*)d_in[0];
  const int*   ei    = (const int*)  d_in[1];
  const int*   batch = (const int*)  d_in[2];
  const float* W1 = (const float*)d_in[3],  *b1  = (const float*)d_in[4];
  const float* W2 = (const float*)d_in[5],  *b2  = (const float*)d_in[6];
  const float* W3 = (const float*)d_in[7],  *b3  = (const float*)d_in[8];
  const float* W4 = (const float*)d_in[9],  *b4  = (const float*)d_in[10];
  const float* cw5= (const float*)d_in[11], *cb5 = (const float*)d_in[12];
  const float* cw6= (const float*)d_in[13], *cb6 = (const float*)d_in[14];
  const float* fw1= (const float*)d_in[15], *fb1 = (const float*)d_in[16];
  const float* fw2= (const float*)d_in[17], *fb2 = (const float*)d_in[18];
  float* logits = (float*)d_out;

  const int TB = 256;
  const int nbN  = (NN + TB - 1)/TB;
  const int nbE  = (NE + TB - 1)/TB;
  const int nbW  = (NN*32 + TB - 1)/TB;
  const int nbSc = (NN + 1023)/1024;
  const int gemmGrid = NN/128;   /* 3125, exact */

  /* launches 1-3: prologue pieces GEMM-1 does not need */
  k_init      <<<nbN, TB>>>();
  k_edge_count<<<nbE, TB>>>(ei);
  k_dis       <<<nbN, TB>>>();
  /* launch 4: GEMM-1 (only needs x, W1) — lands in the ncu -s5-c1 slot */
  k_gemm      <<<gemmGrid, 256>>>(x, 0, W1, FIN);
  /* rest of CSR build */
  k_scan1     <<<nbSc, 1024>>>();
  k_scan2     <<<1, 1024>>>(nbSc);
  k_scan3     <<<nbN, TB>>>();
  k_scatter   <<<nbE, TB>>>(ei);
  k_gcount    <<<nbN, TB>>>(batch);
  k_gstart    <<<1, 32>>>();

  k_agg_tanh <<<nbW, TB>>>(b1, 1, nullptr);
  k_gemm     <<<gemmGrid, 256>>>(nullptr, 1, W2, EMB);
  k_agg_tanh <<<nbW, TB>>>(b2, 2, nullptr);
  k_gemm     <<<gemmGrid, 256>>>(nullptr, 2, W3, EMB);
  k_agg_tanh <<<nbW, TB>>>(b3, 3, W4);     /* fused h4 = x3 . W4 */
  k_agg4     <<<nbN, TB>>>(b4);

  k_select <<<NG, 1024>>>();
  k_conv5  <<<NG*SORTK, 128>>>(cw5, cb5);
  k_conv6  <<<NG, 128>>>(cw6, cb6);
  k_fc1    <<<128, 256>>>(fw1, fb1);
  k_fc2    <<<1, 320>>>(fw2, fb2, logits);
}